// round 10
// baseline (speedup 1.0000x reference)
#include <cuda_runtime.h>
#include <cuda_fp16.h>
#include <cstdint>

// ---------------------------------------------------------------------------
// BiLSTM: B=32, T=512, D=512, H=512. out = [B,T,2H] fp32.
// Phase 1: mma.sync tf32 GEMM  xg = W_ih @ x^T (+bias)      [validated R6-R9]
// Phase 2: recurrent scan in TWO 16-CTA CLUSTERS (one per direction):
//          hardware barrier.cluster sync instead of global atomic barrier,
//          fp16 single-plane W (precision-insensitivity measured R8->R9),
//          W0 frags register-hoisted, h exchanged via L2 (stcg/cp.async.cg).
// ---------------------------------------------------------------------------

#define B_  32
#define T_  512
#define D_  512
#define H_  512
#define G4  2048
#define CLC 16            // CTAs per cluster (= per direction)
#define JT  32            // j columns per CTA
#define SHW 520           // W smem row stride (fp16 elems)
#define SHH 520           // h smem row stride (fp16 elems)

// Scratch (device globals: allocation-free rule)
__device__ float g_xg[2][T_][G4][B_];        // [dir][t][gate*H+j][b]
__device__ __half g_h[2][2][B_][H_];         // [buf][dir][b][j] fp16

// ---------------------------------------------------------------------------
__device__ __forceinline__ uint32_t f2tf32(float f) {
    uint32_t r;
    asm("cvt.rna.tf32.f32 %0, %1;" : "=r"(r) : "f"(f));
    return r;
}
__device__ __forceinline__ void mma_tf32(float* c, const uint32_t* a, const uint32_t* b) {
    asm volatile(
        "mma.sync.aligned.m16n8k8.row.col.f32.tf32.tf32.f32 "
        "{%0,%1,%2,%3}, {%4,%5,%6,%7}, {%8,%9}, {%0,%1,%2,%3};"
        : "+f"(c[0]), "+f"(c[1]), "+f"(c[2]), "+f"(c[3])
        : "r"(a[0]), "r"(a[1]), "r"(a[2]), "r"(a[3]), "r"(b[0]), "r"(b[1]));
}
__device__ __forceinline__ void mma_f16(float* c, const uint32_t* a, const uint32_t* b) {
    asm volatile(
        "mma.sync.aligned.m16n8k16.row.col.f32.f16.f16.f32 "
        "{%0,%1,%2,%3}, {%4,%5,%6,%7}, {%8,%9}, {%0,%1,%2,%3};"
        : "+f"(c[0]), "+f"(c[1]), "+f"(c[2]), "+f"(c[3])
        : "r"(a[0]), "r"(a[1]), "r"(a[2]), "r"(a[3]), "r"(b[0]), "r"(b[1]));
}
__device__ __forceinline__ void ldmx4(uint32_t* r, uint32_t addr) {
    asm volatile("ldmatrix.sync.aligned.m8n8.x4.shared.b16 {%0,%1,%2,%3}, [%4];"
        : "=r"(r[0]), "=r"(r[1]), "=r"(r[2]), "=r"(r[3]) : "r"(addr));
}
__device__ __forceinline__ uint32_t smem_u32(const void* p) {
    uint32_t a;
    asm("{ .reg .u64 t; cvta.to.shared.u64 t, %1; cvt.u32.u64 %0, t; }"
        : "=r"(a) : "l"(p));
    return a;
}
__device__ __forceinline__ void cp_async16(uint32_t dst, const void* src) {
    asm volatile("cp.async.cg.shared.global [%0], [%1], 16;" :: "r"(dst), "l"(src));
}
__device__ __forceinline__ uint16_t hfu(__half v) { return __half_as_ushort(v); }

#define CLUSTER_ARRIVE() asm volatile("barrier.cluster.arrive.aligned;" ::: "memory")
#define CLUSTER_WAIT()   asm volatile("barrier.cluster.wait.aligned;"   ::: "memory")

// fast activations (validated R4/R6-R9)
__device__ __forceinline__ float sigf(float x) {
    return __fdividef(1.f, 1.f + __expf(-x));
}
__device__ __forceinline__ float tanhfast(float x) {
    float ax = fabsf(x);
    float e  = __expf(-2.f * ax);
    float t  = __fdividef(1.f - e, 1.f + e);
    return copysignf(t, x);
}

// ---------------------------------------------------------------------------
// Phase 1: tf32 mma.sync GEMM (validated R6-R9). Unchanged except h-zero init.
// ---------------------------------------------------------------------------
#define SSTR 136
#define KCH  32

__global__ __launch_bounds__(256, 2) void proj_mma_kernel(
    const float* __restrict__ x,
    const float* __restrict__ Wf, const float* __restrict__ Wb,
    const float* __restrict__ bihf, const float* __restrict__ bhhf,
    const float* __restrict__ bihb, const float* __restrict__ bhhb)
{
    __shared__ __align__(16) float A_s[KCH * SSTR];
    __shared__ __align__(16) float B_s[KCH * SSTR];

    const int tid  = threadIdx.x;
    const int lane = tid & 31;
    const int wid  = tid >> 5;
    const int mw   = wid & 1;
    const int nw   = wid >> 1;

    if (blockIdx.x == 0 && blockIdx.y == 0) {
        uint4* z = (uint4*)&g_h[0][0][0][0];     // 8192 uint4 (both bufs/dirs)
#pragma unroll
        for (int i = 0; i < 32; i++)
            z[tid + (i << 8)] = make_uint4(0, 0, 0, 0);
    }

    const int mtile = blockIdx.y;
    const int dir   = mtile >> 4;
    const int mg0   = (mtile & 15) * 128;
    const int t0    = blockIdx.x * 4;
    const float* W  = dir ? Wb : Wf;

    const int lrow = tid >> 1;
    const int lseg = tid & 1;
    const int bL   = lrow & 31;
    const int dtL  = lrow >> 5;
    const float* Arow = W + (size_t)(mg0 + lrow) * D_;
    const float* Brow = x + ((size_t)bL * T_ + t0 + dtL) * D_;

    float acc[4][4][4];
#pragma unroll
    for (int mi = 0; mi < 4; mi++)
#pragma unroll
        for (int ni = 0; ni < 4; ni++)
#pragma unroll
            for (int q = 0; q < 4; q++) acc[mi][ni][q] = 0.f;

    const int frag_k = lane & 3;
    const int frag_r = lane >> 2;

    for (int c = 0; c < D_ / KCH; c++) {
        const int kc = c * KCH;
#pragma unroll
        for (int it = 0; it < 4; it++) {
            int seg = it * 2 + lseg;
            int k0  = seg * 4;
            float4 av = *(const float4*)(Arow + kc + k0);
            float4 bv = *(const float4*)(Brow + kc + k0);
            A_s[(k0 + 0) * SSTR + lrow] = __uint_as_float(f2tf32(av.x));
            A_s[(k0 + 1) * SSTR + lrow] = __uint_as_float(f2tf32(av.y));
            A_s[(k0 + 2) * SSTR + lrow] = __uint_as_float(f2tf32(av.z));
            A_s[(k0 + 3) * SSTR + lrow] = __uint_as_float(f2tf32(av.w));
            B_s[(k0 + 0) * SSTR + lrow] = __uint_as_float(f2tf32(bv.x));
            B_s[(k0 + 1) * SSTR + lrow] = __uint_as_float(f2tf32(bv.y));
            B_s[(k0 + 2) * SSTR + lrow] = __uint_as_float(f2tf32(bv.z));
            B_s[(k0 + 3) * SSTR + lrow] = __uint_as_float(f2tf32(bv.w));
        }
        __syncthreads();

#pragma unroll
        for (int ks = 0; ks < KCH / 8; ks++) {
            const int kb = ks * 8 + frag_k;
            uint32_t afr[4][4], bfr[4][2];
#pragma unroll
            for (int mi = 0; mi < 4; mi++) {
                int m = mw * 64 + mi * 16 + frag_r;
                afr[mi][0] = __float_as_uint(A_s[kb * SSTR + m]);
                afr[mi][1] = __float_as_uint(A_s[kb * SSTR + m + 8]);
                afr[mi][2] = __float_as_uint(A_s[(kb + 4) * SSTR + m]);
                afr[mi][3] = __float_as_uint(A_s[(kb + 4) * SSTR + m + 8]);
            }
#pragma unroll
            for (int ni = 0; ni < 4; ni++) {
                int n = nw * 32 + ni * 8 + frag_r;
                bfr[ni][0] = __float_as_uint(B_s[kb * SSTR + n]);
                bfr[ni][1] = __float_as_uint(B_s[(kb + 4) * SSTR + n]);
            }
#pragma unroll
            for (int mi = 0; mi < 4; mi++)
#pragma unroll
                for (int ni = 0; ni < 4; ni++)
                    mma_tf32(acc[mi][ni], afr[mi], bfr[ni]);
        }
        __syncthreads();
    }

    const int t  = t0 + nw;
    const int bc = 2 * (lane & 3);
#pragma unroll
    for (int mi = 0; mi < 4; mi++) {
        int g0 = mg0 + mw * 64 + mi * 16 + frag_r;
        float bias0 = dir ? (bihb[g0] + bhhb[g0]) : (bihf[g0] + bhhf[g0]);
        float bias1 = dir ? (bihb[g0 + 8] + bhhb[g0 + 8]) : (bihf[g0 + 8] + bhhf[g0 + 8]);
#pragma unroll
        for (int ni = 0; ni < 4; ni++) {
            int b = ni * 8 + bc;
            *(float2*)&g_xg[dir][t][g0][b] =
                make_float2(acc[mi][ni][0] + bias0, acc[mi][ni][1] + bias0);
            *(float2*)&g_xg[dir][t][g0 + 8][b] =
                make_float2(acc[mi][ni][2] + bias1, acc[mi][ni][3] + bias1);
        }
    }
}

// ---------------------------------------------------------------------------
// Phase 2: cluster scan. Grid = 32 CTAs = 2 clusters(16) = 2 dirs.
// CTA: j-tile 32 (m' = gate*32+j, 128 rows), 512 threads = 16 warps
//      = kw(2 K-halves) x wm(8 m16-tiles). Warp tile m16 x n32 x k256.
// W0 fp16 [128][SHW] in smem, frags hoisted to regs (64/thread).
// h: full [32 b][512 k] fp16 copy staged per CTA via cp.async.cg from L2;
//    fresh h written as half2 per cell-thread (stcg).
// Sync: barrier.cluster.arrive (release) / wait (acquire); xg prefetched
//       between arrive and wait to overlap skew.
// ---------------------------------------------------------------------------
#define W0_OFF 0                     // 128*SHW*2        = 133120
#define HS_OFF 133120                // 32*SHH*2         =  33280
#define CS_OFF 166400                // 2*128*36*4       =  36864
#define SMEM_TOT 203264

__global__ __launch_bounds__(512, 1) void lstm_scan_kernel(
    const int*   __restrict__ lengths,
    const float* __restrict__ Whf,
    const float* __restrict__ Whb,
    float*       __restrict__ out)
{
    extern __shared__ __align__(16) char sm[];
    __half* W0_s = (__half*)(sm + W0_OFF);
    float*  C_s  = (float*)(sm + CS_OFF);    // [2][128][36]

    const int tid  = threadIdx.x;
    const int lane = tid & 31;
    const int wid  = tid >> 5;
    const int bx   = blockIdx.x;
    const int dir  = bx >> 4;               // cluster id
    const int j0   = (bx & 15) * JT;        // cta rank within cluster
    const float* W = dir ? Whb : Whf;

    // ---- stage W fp16 into smem (once): row m' = gate*32 + j ----
#pragma unroll
    for (int i = 0; i < 32; i++) {
        int v = tid + i * 512;              // 0..16383 (128 rows x 128 segs)
        int mrow = v >> 7;
        int seg  = v & 127;
        int gate = mrow >> 5, j = mrow & 31;
        float4 wv = __ldg((const float4*)(W + (size_t)((gate << 9) + j0 + j) * D_) + seg);
        uint32_t pA = (uint32_t)hfu(__float2half_rn(wv.x)) |
                      ((uint32_t)hfu(__float2half_rn(wv.y)) << 16);
        uint32_t pB = (uint32_t)hfu(__float2half_rn(wv.z)) |
                      ((uint32_t)hfu(__float2half_rn(wv.w)) << 16);
        *(uint2*)((char*)W0_s + (mrow * SHW + seg * 4) * 2) = make_uint2(pA, pB);
    }
    __syncthreads();

    // warp decomposition
    const int kw = wid >> 3;                // K half
    const int wm = wid & 7;                 // m16 tile
    const int l8 = lane & 7, sel = lane >> 3;
    const uint32_t w0b = smem_u32(W0_s);
    const uint32_t hsb = smem_u32(sm + HS_OFF);
    const uint32_t aoff =
        (uint32_t)((wm * 16 + ((sel & 1) ? 8 : 0) + l8) * SHW
                   + ((sel >> 1) ? 8 : 0) + kw * 256) * 2;
    // B rows = batch: ldmx4 #1 covers b0-15, #2 covers b16-31
    const uint32_t boff1 =
        (uint32_t)(((sel >> 1) * 8 + l8) * SHH + ((sel & 1) ? 8 : 0) + kw * 256) * 2;
    const uint32_t boff2 = boff1 + (uint32_t)(16 * SHH) * 2;

    // ---- hoist W0 fragments (time-invariant): 16 ks x 4 regs ----
    uint32_t a0h[16][4];
#pragma unroll
    for (int ks = 0; ks < 16; ks++)
        ldmx4(a0h[ks], w0b + aoff + ks * 32);

    // cell identity: warp = j pair, lane = b
    const int jA = wid << 1, jB = jA + 1;   // 0..31
    const int b  = lane;
    const int len = __ldg(&lengths[b]);
    float cA = 0.f, hA = 0.f, cB = 0.f, hB = 0.f;
    int cur = 0;

    for (int s = 0; s < T_; s++) {
        const int t = dir ? (T_ - 1 - s) : s;

        __threadfence();          // release prior-step h stores (gpu scope)
        CLUSTER_ARRIVE();

        // ---- prefetch xg between arrive and wait (overlaps cluster skew) ----
        const float* xgp = &g_xg[dir][t][0][0];
        float xiA = __ldg(xgp + (((0 << 9) + j0 + jA) << 5) + b);
        float xfA = __ldg(xgp + (((1 << 9) + j0 + jA) << 5) + b);
        float xgA = __ldg(xgp + (((2 << 9) + j0 + jA) << 5) + b);
        float xoA = __ldg(xgp + (((3 << 9) + j0 + jA) << 5) + b);
        float xiB = __ldg(xgp + (((0 << 9) + j0 + jB) << 5) + b);
        float xfB = __ldg(xgp + (((1 << 9) + j0 + jB) << 5) + b);
        float xgB = __ldg(xgp + (((2 << 9) + j0 + jB) << 5) + b);
        float xoB = __ldg(xgp + (((3 << 9) + j0 + jB) << 5) + b);

        CLUSTER_WAIT();           // acquire: all CTAs' h(s-1) visible in L2

        // ---- stage full h [32][512] fp16 = 2048 x 16B via cp.async.cg ----
        const __half* hg = &g_h[cur][dir][0][0];
#pragma unroll
        for (int i = 0; i < 4; i++) {
            int v = tid + i * 512;          // 0..2047
            int row = v >> 6, cseg = v & 63;
            cp_async16(hsb + (uint32_t)(row * SHH * 2 + cseg * 16),
                       hg + row * H_ + cseg * 8);
        }
        asm volatile("cp.async.commit_group;");
        asm volatile("cp.async.wait_group 0;" ::: "memory");
        __syncthreads();

        // ---- mainloop: 16 k16-steps, W0 from registers ----
        float c0[4] = {0.f, 0.f, 0.f, 0.f};
        float c1[4] = {0.f, 0.f, 0.f, 0.f};
        float c2[4] = {0.f, 0.f, 0.f, 0.f};
        float c3[4] = {0.f, 0.f, 0.f, 0.f};
#pragma unroll
        for (int ks = 0; ks < 16; ks++) {
            uint32_t bf1[4], bf2[4];
            ldmx4(bf1, hsb + boff1 + ks * 32);
            ldmx4(bf2, hsb + boff2 + ks * 32);
            mma_f16(c0, a0h[ks], bf1 + 0);
            mma_f16(c1, a0h[ks], bf1 + 2);
            mma_f16(c2, a0h[ks], bf2 + 0);
            mma_f16(c3, a0h[ks], bf2 + 2);
        }

        // ---- partial C -> C_s[kw][m'][b] ----
        {
            int r = lane >> 2, cp2 = (lane & 3) * 2;
            float* Ck = C_s + kw * (128 * 36) + (wm * 16 + r) * 36;
            *(float2*)&Ck[0 * 8 + cp2]  = make_float2(c0[0], c0[1]);
            *(float2*)&Ck[1 * 8 + cp2]  = make_float2(c1[0], c1[1]);
            *(float2*)&Ck[2 * 8 + cp2]  = make_float2(c2[0], c2[1]);
            *(float2*)&Ck[3 * 8 + cp2]  = make_float2(c3[0], c3[1]);
            float* Ck8 = Ck + 8 * 36;
            *(float2*)&Ck8[0 * 8 + cp2] = make_float2(c0[2], c0[3]);
            *(float2*)&Ck8[1 * 8 + cp2] = make_float2(c1[2], c1[3]);
            *(float2*)&Ck8[2 * 8 + cp2] = make_float2(c2[2], c2[3]);
            *(float2*)&Ck8[3 * 8 + cp2] = make_float2(c3[2], c3[3]);
        }
        __syncthreads();

        // ---- LSTM cells (jA, jB) for lane b ----
        const float* C0p = C_s;
        const float* C1p = C_s + 128 * 36;
        {
            float ri = C0p[(0 * 32 + jA) * 36 + b] + C1p[(0 * 32 + jA) * 36 + b] + xiA;
            float rf = C0p[(1 * 32 + jA) * 36 + b] + C1p[(1 * 32 + jA) * 36 + b] + xfA;
            float rg = C0p[(2 * 32 + jA) * 36 + b] + C1p[(2 * 32 + jA) * 36 + b] + xgA;
            float ro = C0p[(3 * 32 + jA) * 36 + b] + C1p[(3 * 32 + jA) * 36 + b] + xoA;
            float ig = sigf(ri), fg = sigf(rf);
            float gg = tanhfast(rg), og = sigf(ro);
            float cn = fg * cA + ig * gg;
            float hn = og * tanhfast(cn);
            if (t < len) { cA = cn; hA = hn; }
        }
        {
            float ri = C0p[(0 * 32 + jB) * 36 + b] + C1p[(0 * 32 + jB) * 36 + b] + xiB;
            float rf = C0p[(1 * 32 + jB) * 36 + b] + C1p[(1 * 32 + jB) * 36 + b] + xfB;
            float rg = C0p[(2 * 32 + jB) * 36 + b] + C1p[(2 * 32 + jB) * 36 + b] + xgB;
            float ro = C0p[(3 * 32 + jB) * 36 + b] + C1p[(3 * 32 + jB) * 36 + b] + xoB;
            float ig = sigf(ri), fg = sigf(rf);
            float gg = tanhfast(rg), og = sigf(ro);
            float cn = fg * cB + ig * gg;
            float hn = og * tanhfast(cn);
            if (t < len) { cB = cn; hB = hn; }
        }

        // ---- stores: out (float2, adjacent j pair) + h (half2) ----
        *(float2*)&out[((size_t)b * T_ + t) * (2 * H_) + (dir << 9) + j0 + jA] =
            make_float2(hA, hB);
        {
            __half2 hh = __floats2half2_rn(hA, hB);
            __stcg((__half2*)&g_h[cur ^ 1][dir][b][j0 + jA], hh);
        }
        cur ^= 1;
    }
}

// ---------------------------------------------------------------------------
extern "C" void kernel_launch(void* const* d_in, const int* in_sizes, int n_in,
                              void* d_out, int out_size)
{
    const float* x      = (const float*)d_in[0];
    const int*   lens   = (const int*)  d_in[1];
    const float* Wihf   = (const float*)d_in[2];
    const float* Whhf   = (const float*)d_in[3];
    const float* bihf   = (const float*)d_in[4];
    const float* bhhf   = (const float*)d_in[5];
    const float* Wihb   = (const float*)d_in[6];
    const float* Whhb   = (const float*)d_in[7];
    const float* bihb   = (const float*)d_in[8];
    const float* bhhb   = (const float*)d_in[9];
    float* out = (float*)d_out;

    cudaFuncSetAttribute(lstm_scan_kernel,
                         cudaFuncAttributeMaxDynamicSharedMemorySize, SMEM_TOT);
    cudaFuncSetAttribute(lstm_scan_kernel,
                         cudaFuncAttributeNonPortableClusterSizeAllowed, 1);

    dim3 pg(T_ / 4, 32);
    proj_mma_kernel<<<pg, 256>>>(x, Wihf, Wihb, bihf, bhhf, bihb, bhhb);

    cudaLaunchConfig_t cfg = {};
    cfg.gridDim  = dim3(2 * CLC, 1, 1);
    cfg.blockDim = dim3(512, 1, 1);
    cfg.dynamicSmemBytes = SMEM_TOT;
    cfg.stream = 0;
    cudaLaunchAttribute attrs[1];
    attrs[0].id = cudaLaunchAttributeClusterDimension;
    attrs[0].val.clusterDim.x = CLC;
    attrs[0].val.clusterDim.y = 1;
    attrs[0].val.clusterDim.z = 1;
    cfg.attrs = attrs;
    cfg.numAttrs = 1;
    cudaLaunchKernelEx(&cfg, lstm_scan_kernel, lens, Whhf, Whhb, out);
}